// round 9
// baseline (speedup 1.0000x reference)
#include <cuda_runtime.h>
#include <cuda_bf16.h>
#include <cstdint>
#include <math.h>

// ---------------------------------------------------------------------------
// QLayer_Block round 9: bf16 HMMA GEMMs (exact integer math).
// r5-r8 established: throughput ∝ resident warps/SM (16->24->32 warps gave
// 188->159->130us on the attn GEMM). This round: 48 warps/SM via 6 CTAs
// (64x64 tiles, 32KB smem, 42-reg budget).
// ---------------------------------------------------------------------------

namespace {

typedef __nv_bfloat16 bf16;
typedef __nv_bfloat162 bf162;

constexpr int BATCH = 128;
constexpr int NTOK  = 196;
constexpr int DIM   = 768;
constexpr int HID   = 3072;
constexpr int RNK   = 384;
constexpr int KPAD  = 256;
constexpr long TROWS = (long)BATCH * NTOK;   // 25088

// ---- device scratch (integer-valued bf16) ----
__device__ __align__(256) bf16 g_qWattn[256 * KPAD];
__device__ __align__(256) bf16 g_qW1vt[RNK * DIM];
__device__ __align__(256) bf16 g_qW1u [HID * RNK];
__device__ __align__(256) bf16 g_qW2vt[RNK * HID];
__device__ __align__(256) bf16 g_qW2u [DIM * RNK];

__device__ __align__(256) float g_v1a[DIM];
__device__ __align__(256) float g_v2a[DIM];
__device__ __align__(256) float g_g1 [DIM];
__device__ __align__(256) float g_g2 [DIM];
__device__ float g_absmax[8];

__device__ __align__(256) bf16 g_qa1t[(long)BATCH * DIM * KPAD]; // [b][d][npad]
__device__ __align__(256) bf16 g_qx1 [TROWS * DIM];
__device__ __align__(256) bf16 g_qa2 [TROWS * DIM];
__device__ __align__(256) bf16 g_qa3 [TROWS * RNK];
__device__ __align__(256) bf16 g_qa4 [TROWS * HID];
__device__ __align__(256) bf16 g_qa5 [TROWS * RNK];

__device__ __forceinline__ float fqq(float x, float s) {
    float r = rintf(__fdiv_rn(x, s));      // rint == jnp.round (half-to-even)
    return fminf(127.f, fmaxf(-128.f, r));
}
__device__ __forceinline__ float wscale(int slot) {
    return __fadd_rn(__fdiv_rn(g_absmax[slot], 127.f), 1e-8f);
}

// ---------------------------------------------------------------------------
// prep kernels (unchanged)
// ---------------------------------------------------------------------------

__global__ void prep1_k(const float* __restrict__ n1a, const float* __restrict__ n2a,
                        const float* __restrict__ g1,  const float* __restrict__ g2,
                        const float* __restrict__ w0,  const float* __restrict__ w1,
                        const float* __restrict__ w2,  const float* __restrict__ w3,
                        const float* __restrict__ w4) {
    int role = blockIdx.y;
    int tid = threadIdx.x;
    if (role < 4) {
        if (blockIdx.x != 0) return;
        __shared__ float red[256];
        const float* src = (role == 0) ? n1a : (role == 1) ? n2a : (role == 2) ? g1 : g2;
        float* dst = (role == 0) ? g_v1a : (role == 1) ? g_v2a : (role == 2) ? g_g1 : g_g2;
        float m = 0.f;
        for (int i = tid; i < DIM; i += 256) m = fmaxf(m, fabsf(src[i]));
        red[tid] = m;
        __syncthreads();
        for (int s = 128; s > 0; s >>= 1) {
            if (tid < s) red[tid] = fmaxf(red[tid], red[tid + s]);
            __syncthreads();
        }
        float sc = __fadd_rn(__fdiv_rn(red[0], 127.f), 1e-8f);
        for (int i = tid; i < DIM; i += 256)
            dst[i] = __fmul_rn(sc, fqq(src[i], sc));
        return;
    }
    int seg = role - 4;
    const float* w; int n;
    if (seg == 0)      { w = w0; n = NTOK * NTOK; }
    else if (seg == 1) { w = w1; n = RNK * DIM; }
    else if (seg == 2) { w = w2; n = HID * RNK; }
    else if (seg == 3) { w = w3; n = RNK * HID; }
    else               { w = w4; n = DIM * RNK; }
    float m = 0.f;
    for (int i = blockIdx.x * blockDim.x + tid; i < n; i += gridDim.x * blockDim.x)
        m = fmaxf(m, fabsf(w[i]));
#pragma unroll
    for (int o = 16; o; o >>= 1) m = fmaxf(m, __shfl_xor_sync(0xffffffffu, m, o));
    if ((tid & 31) == 0)
        atomicMax((int*)&g_absmax[seg], __float_as_int(m));
}

__global__ void quantw_all_k(const float* __restrict__ w0, const float* __restrict__ w1,
                             const float* __restrict__ w2, const float* __restrict__ w3,
                             const float* __restrict__ w4) {
    int seg = blockIdx.y;
    float s = wscale(seg);
    if (seg == 0) {
        for (int i = blockIdx.x * blockDim.x + threadIdx.x; i < 256 * KPAD;
             i += gridDim.x * blockDim.x) {
            int m = i >> 8, k = i & (KPAD - 1);
            float v = 0.f;
            if (m < NTOK && k < NTOK) v = fqq(w0[m * NTOK + k], s);
            g_qWattn[i] = __float2bfloat16_rn(v);
        }
        return;
    }
    const float* w; bf16* dst; int n;
    if (seg == 1)      { w = w1; dst = g_qW1vt; n = RNK * DIM; }
    else if (seg == 2) { w = w2; dst = g_qW1u;  n = HID * RNK; }
    else if (seg == 3) { w = w3; dst = g_qW2vt; n = RNK * HID; }
    else               { w = w4; dst = g_qW2u;  n = DIM * RNK; }
    for (int i = blockIdx.x * blockDim.x + threadIdx.x; i < n;
         i += gridDim.x * blockDim.x)
        dst[i] = __float2bfloat16_rn(fqq(w[i], s));
}

__global__ void stage0_k(const float* __restrict__ x,
                         const float* __restrict__ nb1,
                         const float* __restrict__ sc) {
    __shared__ float tile[32][33];
    int d0 = blockIdx.x * 32, n0 = blockIdx.y * 32, b = blockIdx.z;
    float s0 = sc[0];
    int tx = threadIdx.x, ty = threadIdx.y;
#pragma unroll
    for (int r = 0; r < 4; ++r) {
        int n = n0 + ty + r * 8, d = d0 + tx;
        float v = 0.f;
        if (n < NTOK) v = x[((long)b * NTOK + n) * DIM + d];
        tile[ty + r * 8][tx] = v;
    }
    __syncthreads();
#pragma unroll
    for (int r = 0; r < 4; ++r) {
        int d = d0 + ty + r * 8, n = n0 + tx;
        float q = 0.f;
        if (n < NTOK) {
            float v = __fadd_rn(__fmul_rn(tile[tx][ty + r * 8], g_v1a[d]), nb1[d]);
            q = fqq(v, s0);
        }
        g_qa1t[((long)b * DIM + d) * KPAD + n] = __float2bfloat16_rn(q);
    }
}

// ---------------------------------------------------------------------------
// bf16 HMMA GEMM core: 64x64 tile, 2-stage, swizzled smem, 6 CTAs/SM
// ---------------------------------------------------------------------------

__device__ __forceinline__ unsigned s2u(const void* p) {
    return (unsigned)__cvta_generic_to_shared(p);
}
__device__ __forceinline__ void cp16(void* d, const void* s) {
    asm volatile("cp.async.cg.shared.global [%0], [%1], 16;\n"
                 :: "r"(s2u(d)), "l"(s) : "memory");
}
__device__ __forceinline__ void cpcommit() {
    asm volatile("cp.async.commit_group;\n" ::: "memory");
}
__device__ __forceinline__ void cpwait0() {
    asm volatile("cp.async.wait_group 0;\n" ::: "memory");
}
__device__ __forceinline__ void ldsm4(unsigned* r, const void* p) {
    asm volatile("ldmatrix.sync.aligned.m8n8.x4.shared.b16 {%0,%1,%2,%3}, [%4];\n"
                 : "=r"(r[0]), "=r"(r[1]), "=r"(r[2]), "=r"(r[3]) : "r"(s2u(p)));
}
__device__ __forceinline__ void mma_bf16(float* c, const unsigned* a,
                                         unsigned b0, unsigned b1) {
    asm volatile(
        "mma.sync.aligned.m16n8k16.row.col.f32.bf16.bf16.f32 "
        "{%0,%1,%2,%3},{%4,%5,%6,%7},{%8,%9},{%0,%1,%2,%3};\n"
        : "+f"(c[0]), "+f"(c[1]), "+f"(c[2]), "+f"(c[3])
        : "r"(a[0]), "r"(a[1]), "r"(a[2]), "r"(a[3]), "r"(b0), "r"(b1));
}

// XOR-swizzled smem address: 128B rows, chunk permuted by row
__device__ __forceinline__ int swz(int row, int chunk) {
    return row * 128 + (((chunk ^ row) & 7) << 4);
}

constexpr int STAGES = 2;
constexpr int A_BYTES = 64 * 128;                  // 8KB / stage
constexpr int B_BYTES = 64 * 128;                  // 8KB / stage
constexpr int STAGE_BYTES = A_BYTES + B_BYTES;     // 16384
constexpr int SMEM_DYN = STAGES * STAGE_BYTES;     // 32768

// STAGE: 0=attn(+res/norm2), 1=fc1_vt, 2=fc1_u(+GELU), 3=fc2_vt, 4=fc2_u(+out)
template <int STAGE>
__global__ void __launch_bounds__(256, 6)
gemm_bf_k(int M, int N, int K,
          const float* __restrict__ sc,
          const float* __restrict__ bias,
          const float* __restrict__ xorg,
          const float* __restrict__ nb2,
          float* __restrict__ outf) {

    extern __shared__ __align__(256) int8_t dsm[];

    const int tid  = threadIdx.x;
    const int warp = tid >> 5, lane = tid & 31;
    const int wm = warp >> 2, wn = warp & 3;      // 2x4 warps, warp tile 32x16
    const int m0 = blockIdx.y * 64;
    const int n0 = blockIdx.x * 64;
    const int bz = blockIdx.z;

    const bf16* Ab;
    const bf16* Bb;
    if (STAGE == 0)      { Ab = g_qWattn; Bb = g_qa1t + (long)bz * DIM * KPAD; }
    else if (STAGE == 1) { Ab = g_qa2;    Bb = g_qW1vt; }
    else if (STAGE == 2) { Ab = g_qa3;    Bb = g_qW1u; }
    else if (STAGE == 3) { Ab = g_qa4;    Bb = g_qW2vt; }
    else                 { Ab = g_qa5;    Bb = g_qW2u; }

    const long rowBytes = (long)K * 2;

    // loader: 64 rows x 8 chunks = 512 chunks per matrix; 2 chunks/thread each
    const int lRow = tid >> 2, lCb = (tid & 3) * 2;

    auto loadTile = [&](int kt, int buf) {
        int8_t* as = dsm + buf * STAGE_BYTES;
        int8_t* bs = as + A_BYTES;
        const int8_t* ag = (const int8_t*)Ab + (long)(m0 + lRow) * rowBytes
                           + (long)kt * 128 + lCb * 16;
        const int8_t* bg = (const int8_t*)Bb + (long)(n0 + lRow) * rowBytes
                           + (long)kt * 128 + lCb * 16;
#pragma unroll
        for (int c = 0; c < 2; ++c) {
            cp16(as + swz(lRow, lCb + c), ag + c * 16);
            cp16(bs + swz(lRow, lCb + c), bg + c * 16);
        }
        cpcommit();
    };

    float acc[2][2][4];
#pragma unroll
    for (int i = 0; i < 2; ++i)
#pragma unroll
        for (int j = 0; j < 2; ++j)
#pragma unroll
            for (int t = 0; t < 4; ++t) acc[i][j][t] = 0.f;

    const int ktiles = K >> 6;      // 64 elements (128B) per k-tile
    loadTile(0, 0);

    const int aRow = lane & 15;
    const int bRow = (lane & 7) + ((lane >> 3) & 1) * 8;
    const int cLane = lane >> 4;                  // chunk sub-offset 0/1

    for (int kt = 0; kt < ktiles; ++kt) {
        cpwait0();
        __syncthreads();               // also orders buffer reuse
        if (kt + 1 < ktiles) loadTile(kt + 1, (kt + 1) & 1);

        int8_t* as = dsm + (kt & 1) * STAGE_BYTES;
        int8_t* bs = as + A_BYTES;

#pragma unroll
        for (int ks = 0; ks < 4; ++ks) {       // 4 x k16 per tile
            unsigned a[2][4], b[4];
#pragma unroll
            for (int i = 0; i < 2; ++i)
                ldsm4(a[i], as + swz(wm * 32 + i * 16 + aRow, ks * 2 + cLane));
            ldsm4(b, bs + swz(wn * 16 + bRow, ks * 2 + cLane));
#pragma unroll
            for (int i = 0; i < 2; ++i) {
                mma_bf16(acc[i][0], a[i], b[0], b[2]);
                mma_bf16(acc[i][1], a[i], b[1], b[3]);
            }
        }
    }

    // ---- epilogue ----
    const float sc1 = sc[1], sc2 = sc[2], sc3 = sc[3], sc4 = sc[4];
    const float sc5 = sc[5], sc6 = sc[6], sc7 = sc[7], sc8 = sc[8], sc9 = sc[9];
    float swp;
    if (STAGE == 0)      swp = sc[0] * wscale(0);
    else if (STAGE == 1) swp = sc2 * wscale(1);
    else if (STAGE == 2) swp = sc4 * wscale(2);
    else if (STAGE == 3) swp = sc6 * wscale(3);
    else                 swp = sc7 * wscale(4);

#pragma unroll
    for (int i = 0; i < 2; ++i) {
        int mrow = m0 + wm * 32 + i * 16 + (lane >> 2);
#pragma unroll
        for (int j = 0; j < 2; ++j) {
            int nn = n0 + wn * 16 + j * 8 + ((lane & 3) << 1);
#pragma unroll
            for (int h = 0; h < 2; ++h) {
                int mm = mrow + h * 8;
                if (mm >= M) continue;
                float a0 = acc[i][j][h * 2 + 0];
                float a1 = acc[i][j][h * 2 + 1];

                if (STAGE == 0) {
                    float bm = bias[mm];
                    float v0 = __fadd_rn(__fmul_rn(a0, swp), bm);
                    float v1 = __fadd_rn(__fmul_rn(a1, swp), bm);
                    float t0 = __fmul_rn(__fmul_rn(sc1, fqq(v0, sc1)), g_g1[nn]);
                    float t1 = __fmul_rn(__fmul_rn(sc1, fqq(v1, sc1)), g_g1[nn + 1]);
                    long idx = ((long)bz * NTOK + mm) * DIM + nn;
                    float2 xo = *(const float2*)(xorg + idx);
                    float q80 = fqq(__fadd_rn(t0, xo.x), sc8);
                    float q81 = fqq(__fadd_rn(t1, xo.y), sc8);
                    *(bf162*)(g_qx1 + idx) =
                        bf162(__float2bfloat16_rn(q80), __float2bfloat16_rn(q81));
                    float x10 = __fmul_rn(sc8, q80), x11 = __fmul_rn(sc8, q81);
                    float h0 = __fadd_rn(__fmul_rn(x10, g_v2a[nn]),     nb2[nn]);
                    float h1 = __fadd_rn(__fmul_rn(x11, g_v2a[nn + 1]), nb2[nn + 1]);
                    *(bf162*)(g_qa2 + idx) =
                        bf162(__float2bfloat16_rn(fqq(h0, sc2)),
                              __float2bfloat16_rn(fqq(h1, sc2)));
                } else if (STAGE == 1 || STAGE == 3) {
                    bf16* dst = (STAGE == 1) ? g_qa3 : g_qa5;
                    float scq = (STAGE == 1) ? sc4 : sc7;
                    float v0 = __fadd_rn(__fmul_rn(a0, swp), bias[nn]);
                    float v1 = __fadd_rn(__fmul_rn(a1, swp), bias[nn + 1]);
                    *(bf162*)(dst + (long)mm * RNK + nn) =
                        bf162(__float2bfloat16_rn(fqq(v0, scq)),
                              __float2bfloat16_rn(fqq(v1, scq)));
                } else if (STAGE == 2) {
                    float v0 = __fadd_rn(__fmul_rn(a0, swp), bias[nn]);
                    float v1 = __fadd_rn(__fmul_rn(a1, swp), bias[nn + 1]);
                    float t0 = __fmul_rn(sc5, fqq(v0, sc5));
                    float t1 = __fmul_rn(sc5, fqq(v1, sc5));
                    float g0 = __fmul_rn(__fmul_rn(0.5f, t0),
                               __fadd_rn(1.f, erff(__fmul_rn(t0, 0.70710678118654752f))));
                    float g1v = __fmul_rn(__fmul_rn(0.5f, t1),
                               __fadd_rn(1.f, erff(__fmul_rn(t1, 0.70710678118654752f))));
                    *(bf162*)(g_qa4 + (long)mm * HID + nn) =
                        bf162(__float2bfloat16_rn(fqq(g0, sc6)),
                              __float2bfloat16_rn(fqq(g1v, sc6)));
                } else {
                    float v0 = __fadd_rn(__fmul_rn(a0, swp), bias[nn]);
                    float v1 = __fadd_rn(__fmul_rn(a1, swp), bias[nn + 1]);
                    float t0 = __fmul_rn(__fmul_rn(sc3, fqq(v0, sc3)), g_g2[nn]);
                    float t1 = __fmul_rn(__fmul_rn(sc3, fqq(v1, sc3)), g_g2[nn + 1]);
                    long idx = (long)mm * DIM + nn;
                    bf162 qx = *(const bf162*)(g_qx1 + idx);
                    float r0 = __fadd_rn(t0, __fmul_rn(sc8, __bfloat162float(qx.x)));
                    float r1 = __fadd_rn(t1, __fmul_rn(sc8, __bfloat162float(qx.y)));
                    float2 o;
                    o.x = __fmul_rn(sc9, fqq(r0, sc9));
                    o.y = __fmul_rn(sc9, fqq(r1, sc9));
                    *(float2*)(outf + idx) = o;
                }
            }
        }
    }
}

} // anonymous namespace

// ---------------------------------------------------------------------------
extern "C" void kernel_launch(void* const* d_in, const int* in_sizes, int n_in,
                              void* d_out, int out_size) {
    const float* x    = (const float*)d_in[0];
    const float* n1a  = (const float*)d_in[1];
    const float* n1b  = (const float*)d_in[2];
    const float* attw = (const float*)d_in[3];
    const float* attb = (const float*)d_in[4];
    const float* g1   = (const float*)d_in[5];
    const float* n2a  = (const float*)d_in[6];
    const float* n2b  = (const float*)d_in[7];
    const float* w1vt = (const float*)d_in[8];
    const float* b1vt = (const float*)d_in[9];
    const float* w1u  = (const float*)d_in[10];
    const float* b1u  = (const float*)d_in[11];
    const float* w2vt = (const float*)d_in[12];
    const float* b2vt = (const float*)d_in[13];
    const float* w2u  = (const float*)d_in[14];
    const float* b2u  = (const float*)d_in[15];
    const float* g2   = (const float*)d_in[16];
    const float* sc   = (const float*)d_in[17];
    float* out = (float*)d_out;

    cudaFuncSetAttribute(gemm_bf_k<0>, cudaFuncAttributeMaxDynamicSharedMemorySize, SMEM_DYN);
    cudaFuncSetAttribute(gemm_bf_k<1>, cudaFuncAttributeMaxDynamicSharedMemorySize, SMEM_DYN);
    cudaFuncSetAttribute(gemm_bf_k<2>, cudaFuncAttributeMaxDynamicSharedMemorySize, SMEM_DYN);
    cudaFuncSetAttribute(gemm_bf_k<3>, cudaFuncAttributeMaxDynamicSharedMemorySize, SMEM_DYN);
    cudaFuncSetAttribute(gemm_bf_k<4>, cudaFuncAttributeMaxDynamicSharedMemorySize, SMEM_DYN);

    prep1_k<<<dim3(96, 9), 256>>>(n1a, n2a, g1, g2, attw, w1vt, w1u, w2vt, w2u);
    quantw_all_k<<<dim3(128, 5), 256>>>(attw, w1vt, w1u, w2vt, w2u);

    {   // stage 0: norm1 + fq(s0), transposed/padded to [b][d][256]
        dim3 grid(DIM / 32, KPAD / 32, BATCH);
        dim3 blk(32, 8);
        stage0_k<<<grid, blk>>>(x, n1b, sc);
    }
    {   // attn: per-batch C[196,768], K=256
        dim3 grid(DIM / 64, 4, BATCH);
        gemm_bf_k<0><<<grid, 256, SMEM_DYN>>>(NTOK, DIM, KPAD, sc, attb, x, n2b, nullptr);
    }
    {   // fc1_vt
        dim3 grid(RNK / 64, (int)(TROWS / 64), 1);
        gemm_bf_k<1><<<grid, 256, SMEM_DYN>>>((int)TROWS, RNK, DIM, sc, b1vt, x, n2b, nullptr);
    }
    {   // fc1_u (+GELU)
        dim3 grid(HID / 64, (int)(TROWS / 64), 1);
        gemm_bf_k<2><<<grid, 256, SMEM_DYN>>>((int)TROWS, HID, RNK, sc, b1u, x, n2b, nullptr);
    }
    {   // fc2_vt
        dim3 grid(RNK / 64, (int)(TROWS / 64), 1);
        gemm_bf_k<3><<<grid, 256, SMEM_DYN>>>((int)TROWS, RNK, HID, sc, b2vt, x, n2b, nullptr);
    }
    {   // fc2_u + gamma2 + residual -> out
        dim3 grid(DIM / 64, (int)(TROWS / 64), 1);
        gemm_bf_k<4><<<grid, 256, SMEM_DYN>>>((int)TROWS, DIM, RNK, sc, b2u, x, n2b, out);
    }
}

// round 10
// speedup vs baseline: 1.0079x; 1.0079x over previous
#include <cuda_runtime.h>
#include <cuda_bf16.h>
#include <cstdint>
#include <math.h>

// ---------------------------------------------------------------------------
// QLayer_Block round 10: bf16 HMMA GEMMs (exact integer math).
// r8/r9 evidence: attn GEMM prefers 64x64 tiles @6 CTAs/SM (112us), fc GEMMs
// prefer 128x64 @4 CTAs/SM (total regressed 19us on 64x64). This round uses
// per-stage configs via one template, plus induction-variable global pointers
// to remove 64-bit address IMADs from the k-loop (alu was 30.7%).
// ---------------------------------------------------------------------------

namespace {

typedef __nv_bfloat16 bf16;
typedef __nv_bfloat162 bf162;

constexpr int BATCH = 128;
constexpr int NTOK  = 196;
constexpr int DIM   = 768;
constexpr int HID   = 3072;
constexpr int RNK   = 384;
constexpr int KPAD  = 256;
constexpr long TROWS = (long)BATCH * NTOK;   // 25088

// ---- device scratch (integer-valued bf16) ----
__device__ __align__(256) bf16 g_qWattn[256 * KPAD];
__device__ __align__(256) bf16 g_qW1vt[RNK * DIM];
__device__ __align__(256) bf16 g_qW1u [HID * RNK];
__device__ __align__(256) bf16 g_qW2vt[RNK * HID];
__device__ __align__(256) bf16 g_qW2u [DIM * RNK];

__device__ __align__(256) float g_v1a[DIM];
__device__ __align__(256) float g_v2a[DIM];
__device__ __align__(256) float g_g1 [DIM];
__device__ __align__(256) float g_g2 [DIM];
__device__ float g_absmax[8];

__device__ __align__(256) bf16 g_qa1t[(long)BATCH * DIM * KPAD]; // [b][d][npad]
__device__ __align__(256) bf16 g_qx1 [TROWS * DIM];
__device__ __align__(256) bf16 g_qa2 [TROWS * DIM];
__device__ __align__(256) bf16 g_qa3 [TROWS * RNK];
__device__ __align__(256) bf16 g_qa4 [TROWS * HID];
__device__ __align__(256) bf16 g_qa5 [TROWS * RNK];

__device__ __forceinline__ float fqq(float x, float s) {
    float r = rintf(__fdiv_rn(x, s));      // rint == jnp.round (half-to-even)
    return fminf(127.f, fmaxf(-128.f, r));
}
__device__ __forceinline__ float wscale(int slot) {
    return __fadd_rn(__fdiv_rn(g_absmax[slot], 127.f), 1e-8f);
}

// ---------------------------------------------------------------------------
// prep kernels (unchanged)
// ---------------------------------------------------------------------------

__global__ void prep1_k(const float* __restrict__ n1a, const float* __restrict__ n2a,
                        const float* __restrict__ g1,  const float* __restrict__ g2,
                        const float* __restrict__ w0,  const float* __restrict__ w1,
                        const float* __restrict__ w2,  const float* __restrict__ w3,
                        const float* __restrict__ w4) {
    int role = blockIdx.y;
    int tid = threadIdx.x;
    if (role < 4) {
        if (blockIdx.x != 0) return;
        __shared__ float red[256];
        const float* src = (role == 0) ? n1a : (role == 1) ? n2a : (role == 2) ? g1 : g2;
        float* dst = (role == 0) ? g_v1a : (role == 1) ? g_v2a : (role == 2) ? g_g1 : g_g2;
        float m = 0.f;
        for (int i = tid; i < DIM; i += 256) m = fmaxf(m, fabsf(src[i]));
        red[tid] = m;
        __syncthreads();
        for (int s = 128; s > 0; s >>= 1) {
            if (tid < s) red[tid] = fmaxf(red[tid], red[tid + s]);
            __syncthreads();
        }
        float sc = __fadd_rn(__fdiv_rn(red[0], 127.f), 1e-8f);
        for (int i = tid; i < DIM; i += 256)
            dst[i] = __fmul_rn(sc, fqq(src[i], sc));
        return;
    }
    int seg = role - 4;
    const float* w; int n;
    if (seg == 0)      { w = w0; n = NTOK * NTOK; }
    else if (seg == 1) { w = w1; n = RNK * DIM; }
    else if (seg == 2) { w = w2; n = HID * RNK; }
    else if (seg == 3) { w = w3; n = RNK * HID; }
    else               { w = w4; n = DIM * RNK; }
    float m = 0.f;
    for (int i = blockIdx.x * blockDim.x + tid; i < n; i += gridDim.x * blockDim.x)
        m = fmaxf(m, fabsf(w[i]));
#pragma unroll
    for (int o = 16; o; o >>= 1) m = fmaxf(m, __shfl_xor_sync(0xffffffffu, m, o));
    if ((tid & 31) == 0)
        atomicMax((int*)&g_absmax[seg], __float_as_int(m));
}

__global__ void quantw_all_k(const float* __restrict__ w0, const float* __restrict__ w1,
                             const float* __restrict__ w2, const float* __restrict__ w3,
                             const float* __restrict__ w4) {
    int seg = blockIdx.y;
    float s = wscale(seg);
    if (seg == 0) {
        for (int i = blockIdx.x * blockDim.x + threadIdx.x; i < 256 * KPAD;
             i += gridDim.x * blockDim.x) {
            int m = i >> 8, k = i & (KPAD - 1);
            float v = 0.f;
            if (m < NTOK && k < NTOK) v = fqq(w0[m * NTOK + k], s);
            g_qWattn[i] = __float2bfloat16_rn(v);
        }
        return;
    }
    const float* w; bf16* dst; int n;
    if (seg == 1)      { w = w1; dst = g_qW1vt; n = RNK * DIM; }
    else if (seg == 2) { w = w2; dst = g_qW1u;  n = HID * RNK; }
    else if (seg == 3) { w = w3; dst = g_qW2vt; n = RNK * HID; }
    else               { w = w4; dst = g_qW2u;  n = DIM * RNK; }
    for (int i = blockIdx.x * blockDim.x + threadIdx.x; i < n;
         i += gridDim.x * blockDim.x)
        dst[i] = __float2bfloat16_rn(fqq(w[i], s));
}

__global__ void stage0_k(const float* __restrict__ x,
                         const float* __restrict__ nb1,
                         const float* __restrict__ sc) {
    __shared__ float tile[32][33];
    int d0 = blockIdx.x * 32, n0 = blockIdx.y * 32, b = blockIdx.z;
    float s0 = sc[0];
    int tx = threadIdx.x, ty = threadIdx.y;
#pragma unroll
    for (int r = 0; r < 4; ++r) {
        int n = n0 + ty + r * 8, d = d0 + tx;
        float v = 0.f;
        if (n < NTOK) v = x[((long)b * NTOK + n) * DIM + d];
        tile[ty + r * 8][tx] = v;
    }
    __syncthreads();
#pragma unroll
    for (int r = 0; r < 4; ++r) {
        int d = d0 + ty + r * 8, n = n0 + tx;
        float q = 0.f;
        if (n < NTOK) {
            float v = __fadd_rn(__fmul_rn(tile[tx][ty + r * 8], g_v1a[d]), nb1[d]);
            q = fqq(v, s0);
        }
        g_qa1t[((long)b * DIM + d) * KPAD + n] = __float2bfloat16_rn(q);
    }
}

// ---------------------------------------------------------------------------
// bf16 HMMA GEMM core, parameterized tile: BM x 64, 2-stage swizzled smem
// ---------------------------------------------------------------------------

__device__ __forceinline__ unsigned s2u(const void* p) {
    return (unsigned)__cvta_generic_to_shared(p);
}
__device__ __forceinline__ void cp16(void* d, const void* s) {
    asm volatile("cp.async.cg.shared.global [%0], [%1], 16;\n"
                 :: "r"(s2u(d)), "l"(s) : "memory");
}
__device__ __forceinline__ void cpcommit() {
    asm volatile("cp.async.commit_group;\n" ::: "memory");
}
__device__ __forceinline__ void cpwait0() {
    asm volatile("cp.async.wait_group 0;\n" ::: "memory");
}
__device__ __forceinline__ void ldsm4(unsigned* r, const void* p) {
    asm volatile("ldmatrix.sync.aligned.m8n8.x4.shared.b16 {%0,%1,%2,%3}, [%4];\n"
                 : "=r"(r[0]), "=r"(r[1]), "=r"(r[2]), "=r"(r[3]) : "r"(s2u(p)));
}
__device__ __forceinline__ void mma_bf16(float* c, const unsigned* a,
                                         unsigned b0, unsigned b1) {
    asm volatile(
        "mma.sync.aligned.m16n8k16.row.col.f32.bf16.bf16.f32 "
        "{%0,%1,%2,%3},{%4,%5,%6,%7},{%8,%9},{%0,%1,%2,%3};\n"
        : "+f"(c[0]), "+f"(c[1]), "+f"(c[2]), "+f"(c[3])
        : "r"(a[0]), "r"(a[1]), "r"(a[2]), "r"(a[3]), "r"(b0), "r"(b1));
}

// XOR-swizzled smem address: 128B rows, chunk permuted by row
__device__ __forceinline__ int swz(int row, int chunk) {
    return row * 128 + (((chunk ^ row) & 7) << 4);
}

// STAGE: 0=attn(+res/norm2), 1=fc1_vt, 2=fc1_u(+GELU), 3=fc2_vt, 4=fc2_u(+out)
// BM: CTA tile rows (64 or 128); tile cols fixed at 64.
template <int STAGE, int BM, int OCC>
__global__ void __launch_bounds__(256, OCC)
gemm_bf_k(int M, int N, int K,
          const float* __restrict__ sc,
          const float* __restrict__ bias,
          const float* __restrict__ xorg,
          const float* __restrict__ nb2,
          float* __restrict__ outf) {

    constexpr int A_BYTES = BM * 128;
    constexpr int STAGE_BYTES = A_BYTES + 64 * 128;
    constexpr int NJ = (BM == 128) ? 4 : 2;   // 8-col groups per warp
    constexpr int NB = NJ / 2;                // B ldsm4 per ks

    extern __shared__ __align__(256) int8_t dsm[];

    const int tid  = threadIdx.x;
    const int warp = tid >> 5, lane = tid & 31;
    const int wm = (BM == 128) ? (warp >> 1) : (warp >> 2);
    const int wn = (BM == 128) ? (warp & 1)  : (warp & 3);
    const int m0 = blockIdx.y * BM;
    const int n0 = blockIdx.x * 64;
    const int bz = blockIdx.z;

    const bf16* Ab;
    const bf16* Bb;
    if (STAGE == 0)      { Ab = g_qWattn; Bb = g_qa1t + (long)bz * DIM * KPAD; }
    else if (STAGE == 1) { Ab = g_qa2;    Bb = g_qW1vt; }
    else if (STAGE == 2) { Ab = g_qa3;    Bb = g_qW1u; }
    else if (STAGE == 3) { Ab = g_qa4;    Bb = g_qW2vt; }
    else                 { Ab = g_qa5;    Bb = g_qW2u; }

    const long rowBytes = (long)K * 2;

    // ---- loader setup: induction pointers, smem offsets fixed per thread ----
    // BM==128: A 4 chunks/thread (rows tid>>1), B 2 chunks/thread (rows tid>>2)
    // BM==64 : A 2 chunks/thread and B 2 chunks/thread (rows tid>>2)
    const int aRowL = (BM == 128) ? (tid >> 1) : (tid >> 2);
    const int aCbL  = (BM == 128) ? ((tid & 1) * 4) : ((tid & 3) * 2);
    const int bRowL = tid >> 2;
    const int bCbL  = (tid & 3) * 2;
    constexpr int ACH = (BM == 128) ? 4 : 2;   // A chunks per thread

    const int8_t* agp = (const int8_t*)Ab + (long)(m0 + aRowL) * rowBytes + aCbL * 16;
    const int8_t* bgp = (const int8_t*)Bb + (long)(n0 + bRowL) * rowBytes + bCbL * 16;

    int sA[ACH], sB[2];
#pragma unroll
    for (int c = 0; c < ACH; ++c) sA[c] = swz(aRowL, aCbL + c);
#pragma unroll
    for (int c = 0; c < 2; ++c) sB[c] = swz(bRowL, bCbL + c) + A_BYTES;

    auto loadTile = [&](int buf) {
        int8_t* base = dsm + buf * STAGE_BYTES;
#pragma unroll
        for (int c = 0; c < ACH; ++c) cp16(base + sA[c], agp + c * 16);
#pragma unroll
        for (int c = 0; c < 2; ++c)  cp16(base + sB[c], bgp + c * 16);
        cpcommit();
        agp += 128;
        bgp += 128;
    };

    float acc[2][NJ][4];
#pragma unroll
    for (int i = 0; i < 2; ++i)
#pragma unroll
        for (int j = 0; j < NJ; ++j)
#pragma unroll
            for (int t = 0; t < 4; ++t) acc[i][j][t] = 0.f;

    const int ktiles = K >> 6;      // 64 elements (128B) per k-tile
    loadTile(0);

    const int aRow = lane & 15;
    const int bRow = (lane & 7) + ((lane >> 3) & 1) * 8;
    const int cLane = lane >> 4;

    for (int kt = 0; kt < ktiles; ++kt) {
        cpwait0();
        __syncthreads();               // also orders buffer reuse
        if (kt + 1 < ktiles) loadTile((kt + 1) & 1);

        int8_t* as = dsm + (kt & 1) * STAGE_BYTES;
        int8_t* bs = as + A_BYTES;

#pragma unroll
        for (int ks = 0; ks < 4; ++ks) {       // 4 x k16 per tile
            unsigned a[2][4], b[NB][4];
#pragma unroll
            for (int i = 0; i < 2; ++i)
                ldsm4(a[i], as + swz(wm * 32 + i * 16 + aRow, ks * 2 + cLane));
#pragma unroll
            for (int jp = 0; jp < NB; ++jp)
                ldsm4(b[jp], bs + swz(wn * (NJ * 8) + jp * 16 + bRow, ks * 2 + cLane));
#pragma unroll
            for (int jp = 0; jp < NB; ++jp)
#pragma unroll
                for (int i = 0; i < 2; ++i) {
                    mma_bf16(acc[i][jp * 2 + 0], a[i], b[jp][0], b[jp][2]);
                    mma_bf16(acc[i][jp * 2 + 1], a[i], b[jp][1], b[jp][3]);
                }
        }
    }

    // ---- epilogue ----
    const float sc1 = sc[1], sc2 = sc[2], sc3 = sc[3], sc4 = sc[4];
    const float sc5 = sc[5], sc6 = sc[6], sc7 = sc[7], sc8 = sc[8], sc9 = sc[9];
    float swp;
    if (STAGE == 0)      swp = sc[0] * wscale(0);
    else if (STAGE == 1) swp = sc2 * wscale(1);
    else if (STAGE == 2) swp = sc4 * wscale(2);
    else if (STAGE == 3) swp = sc6 * wscale(3);
    else                 swp = sc7 * wscale(4);

#pragma unroll
    for (int i = 0; i < 2; ++i) {
        int mrow = m0 + wm * 32 + i * 16 + (lane >> 2);
#pragma unroll
        for (int j = 0; j < NJ; ++j) {
            int nn = n0 + wn * (NJ * 8) + j * 8 + ((lane & 3) << 1);
#pragma unroll
            for (int h = 0; h < 2; ++h) {
                int mm = mrow + h * 8;
                if (mm >= M) continue;
                float a0 = acc[i][j][h * 2 + 0];
                float a1 = acc[i][j][h * 2 + 1];

                if (STAGE == 0) {
                    float bm = bias[mm];
                    float v0 = __fadd_rn(__fmul_rn(a0, swp), bm);
                    float v1 = __fadd_rn(__fmul_rn(a1, swp), bm);
                    float t0 = __fmul_rn(__fmul_rn(sc1, fqq(v0, sc1)), g_g1[nn]);
                    float t1 = __fmul_rn(__fmul_rn(sc1, fqq(v1, sc1)), g_g1[nn + 1]);
                    long idx = ((long)bz * NTOK + mm) * DIM + nn;
                    float2 xo = *(const float2*)(xorg + idx);
                    float q80 = fqq(__fadd_rn(t0, xo.x), sc8);
                    float q81 = fqq(__fadd_rn(t1, xo.y), sc8);
                    *(bf162*)(g_qx1 + idx) =
                        bf162(__float2bfloat16_rn(q80), __float2bfloat16_rn(q81));
                    float x10 = __fmul_rn(sc8, q80), x11 = __fmul_rn(sc8, q81);
                    float h0 = __fadd_rn(__fmul_rn(x10, g_v2a[nn]),     nb2[nn]);
                    float h1 = __fadd_rn(__fmul_rn(x11, g_v2a[nn + 1]), nb2[nn + 1]);
                    *(bf162*)(g_qa2 + idx) =
                        bf162(__float2bfloat16_rn(fqq(h0, sc2)),
                              __float2bfloat16_rn(fqq(h1, sc2)));
                } else if (STAGE == 1 || STAGE == 3) {
                    bf16* dst = (STAGE == 1) ? g_qa3 : g_qa5;
                    float scq = (STAGE == 1) ? sc4 : sc7;
                    float v0 = __fadd_rn(__fmul_rn(a0, swp), bias[nn]);
                    float v1 = __fadd_rn(__fmul_rn(a1, swp), bias[nn + 1]);
                    *(bf162*)(dst + (long)mm * RNK + nn) =
                        bf162(__float2bfloat16_rn(fqq(v0, scq)),
                              __float2bfloat16_rn(fqq(v1, scq)));
                } else if (STAGE == 2) {
                    float v0 = __fadd_rn(__fmul_rn(a0, swp), bias[nn]);
                    float v1 = __fadd_rn(__fmul_rn(a1, swp), bias[nn + 1]);
                    float t0 = __fmul_rn(sc5, fqq(v0, sc5));
                    float t1 = __fmul_rn(sc5, fqq(v1, sc5));
                    float g0 = __fmul_rn(__fmul_rn(0.5f, t0),
                               __fadd_rn(1.f, erff(__fmul_rn(t0, 0.70710678118654752f))));
                    float g1v = __fmul_rn(__fmul_rn(0.5f, t1),
                               __fadd_rn(1.f, erff(__fmul_rn(t1, 0.70710678118654752f))));
                    *(bf162*)(g_qa4 + (long)mm * HID + nn) =
                        bf162(__float2bfloat16_rn(fqq(g0, sc6)),
                              __float2bfloat16_rn(fqq(g1v, sc6)));
                } else {
                    float v0 = __fadd_rn(__fmul_rn(a0, swp), bias[nn]);
                    float v1 = __fadd_rn(__fmul_rn(a1, swp), bias[nn + 1]);
                    float t0 = __fmul_rn(__fmul_rn(sc3, fqq(v0, sc3)), g_g2[nn]);
                    float t1 = __fmul_rn(__fmul_rn(sc3, fqq(v1, sc3)), g_g2[nn + 1]);
                    long idx = (long)mm * DIM + nn;
                    bf162 qx = *(const bf162*)(g_qx1 + idx);
                    float r0 = __fadd_rn(t0, __fmul_rn(sc8, __bfloat162float(qx.x)));
                    float r1 = __fadd_rn(t1, __fmul_rn(sc8, __bfloat162float(qx.y)));
                    float2 o;
                    o.x = __fmul_rn(sc9, fqq(r0, sc9));
                    o.y = __fmul_rn(sc9, fqq(r1, sc9));
                    *(float2*)(outf + idx) = o;
                }
            }
        }
    }
}

constexpr int SMEM64  = 2 * (64 * 128 + 64 * 128);    // 32768
constexpr int SMEM128 = 2 * (128 * 128 + 64 * 128);   // 49152

} // anonymous namespace

// ---------------------------------------------------------------------------
extern "C" void kernel_launch(void* const* d_in, const int* in_sizes, int n_in,
                              void* d_out, int out_size) {
    const float* x    = (const float*)d_in[0];
    const float* n1a  = (const float*)d_in[1];
    const float* n1b  = (const float*)d_in[2];
    const float* attw = (const float*)d_in[3];
    const float* attb = (const float*)d_in[4];
    const float* g1   = (const float*)d_in[5];
    const float* n2a  = (const float*)d_in[6];
    const float* n2b  = (const float*)d_in[7];
    const float* w1vt = (const float*)d_in[8];
    const float* b1vt = (const float*)d_in[9];
    const float* w1u  = (const float*)d_in[10];
    const float* b1u  = (const float*)d_in[11];
    const float* w2vt = (const float*)d_in[12];
    const float* b2vt = (const float*)d_in[13];
    const float* w2u  = (const float*)d_in[14];
    const float* b2u  = (const float*)d_in[15];
    const float* g2   = (const float*)d_in[16];
    const float* sc   = (const float*)d_in[17];
    float* out = (float*)d_out;

    cudaFuncSetAttribute(gemm_bf_k<0, 64, 6>,
                         cudaFuncAttributeMaxDynamicSharedMemorySize, SMEM64);
    cudaFuncSetAttribute(gemm_bf_k<1, 128, 4>,
                         cudaFuncAttributeMaxDynamicSharedMemorySize, SMEM128);
    cudaFuncSetAttribute(gemm_bf_k<2, 128, 4>,
                         cudaFuncAttributeMaxDynamicSharedMemorySize, SMEM128);
    cudaFuncSetAttribute(gemm_bf_k<3, 128, 4>,
                         cudaFuncAttributeMaxDynamicSharedMemorySize, SMEM128);
    cudaFuncSetAttribute(gemm_bf_k<4, 128, 4>,
                         cudaFuncAttributeMaxDynamicSharedMemorySize, SMEM128);

    prep1_k<<<dim3(96, 9), 256>>>(n1a, n2a, g1, g2, attw, w1vt, w1u, w2vt, w2u);
    quantw_all_k<<<dim3(128, 5), 256>>>(attw, w1vt, w1u, w2vt, w2u);

    {   // stage 0: norm1 + fq(s0), transposed/padded to [b][d][256]
        dim3 grid(DIM / 32, KPAD / 32, BATCH);
        dim3 blk(32, 8);
        stage0_k<<<grid, blk>>>(x, n1b, sc);
    }
    {   // attn: per-batch C[196,768], K=256 — 64x64 tiles, 6 CTAs/SM
        dim3 grid(DIM / 64, 4, BATCH);
        gemm_bf_k<0, 64, 6><<<grid, 256, SMEM64>>>(NTOK, DIM, KPAD, sc, attb, x, n2b, nullptr);
    }
    {   // fc1_vt — 128x64 tiles, 4 CTAs/SM
        dim3 grid(RNK / 64, (int)(TROWS / 128), 1);
        gemm_bf_k<1, 128, 4><<<grid, 256, SMEM128>>>((int)TROWS, RNK, DIM, sc, b1vt, x, n2b, nullptr);
    }
    {   // fc1_u (+GELU)
        dim3 grid(HID / 64, (int)(TROWS / 128), 1);
        gemm_bf_k<2, 128, 4><<<grid, 256, SMEM128>>>((int)TROWS, HID, RNK, sc, b1u, x, n2b, nullptr);
    }
    {   // fc2_vt
        dim3 grid(RNK / 64, (int)(TROWS / 128), 1);
        gemm_bf_k<3, 128, 4><<<grid, 256, SMEM128>>>((int)TROWS, RNK, HID, sc, b2vt, x, n2b, nullptr);
    }
    {   // fc2_u + gamma2 + residual -> out
        dim3 grid(DIM / 64, (int)(TROWS / 128), 1);
        gemm_bf_k<4, 128, 4><<<grid, 256, SMEM128>>>((int)TROWS, DIM, RNK, sc, b2u, x, n2b, out);
    }
}

// round 11
// speedup vs baseline: 1.1406x; 1.1316x over previous
#include <cuda_runtime.h>
#include <cuda_bf16.h>
#include <cstdint>
#include <math.h>

// ---------------------------------------------------------------------------
// QLayer_Block round 11: bf16 HMMA GEMMs (exact integer math).
// Model after r8-r10: attn GEMM is latency-bound (wants max warps; 64x64@6),
// fc GEMMs are issue-mix-bound (want more MMAs per LDSM). fc now uses
// 128x128 tiles / 512 threads / warp tile 32x32 (MMA:LDSM 16:4, 2 CTAs/SM).
// stage0 rewritten with paired bf162 stores.
// ---------------------------------------------------------------------------

namespace {

typedef __nv_bfloat16 bf16;
typedef __nv_bfloat162 bf162;

constexpr int BATCH = 128;
constexpr int NTOK  = 196;
constexpr int DIM   = 768;
constexpr int HID   = 3072;
constexpr int RNK   = 384;
constexpr int KPAD  = 256;
constexpr long TROWS = (long)BATCH * NTOK;   // 25088

// ---- device scratch (integer-valued bf16) ----
__device__ __align__(256) bf16 g_qWattn[256 * KPAD];
__device__ __align__(256) bf16 g_qW1vt[RNK * DIM];
__device__ __align__(256) bf16 g_qW1u [HID * RNK];
__device__ __align__(256) bf16 g_qW2vt[RNK * HID];
__device__ __align__(256) bf16 g_qW2u [DIM * RNK];

__device__ __align__(256) float g_v1a[DIM];
__device__ __align__(256) float g_v2a[DIM];
__device__ __align__(256) float g_g1 [DIM];
__device__ __align__(256) float g_g2 [DIM];
__device__ float g_absmax[8];

__device__ __align__(256) bf16 g_qa1t[(long)BATCH * DIM * KPAD]; // [b][d][npad]
__device__ __align__(256) bf16 g_qx1 [TROWS * DIM];
__device__ __align__(256) bf16 g_qa2 [TROWS * DIM];
__device__ __align__(256) bf16 g_qa3 [TROWS * RNK];
__device__ __align__(256) bf16 g_qa4 [TROWS * HID];
__device__ __align__(256) bf16 g_qa5 [TROWS * RNK];

__device__ __forceinline__ float fqq(float x, float s) {
    float r = rintf(__fdiv_rn(x, s));      // rint == jnp.round (half-to-even)
    return fminf(127.f, fmaxf(-128.f, r));
}
__device__ __forceinline__ float wscale(int slot) {
    return __fadd_rn(__fdiv_rn(g_absmax[slot], 127.f), 1e-8f);
}

// ---------------------------------------------------------------------------
// prep kernels
// ---------------------------------------------------------------------------

__global__ void prep1_k(const float* __restrict__ n1a, const float* __restrict__ n2a,
                        const float* __restrict__ g1,  const float* __restrict__ g2,
                        const float* __restrict__ w0,  const float* __restrict__ w1,
                        const float* __restrict__ w2,  const float* __restrict__ w3,
                        const float* __restrict__ w4) {
    int role = blockIdx.y;
    int tid = threadIdx.x;
    if (role < 4) {
        if (blockIdx.x != 0) return;
        __shared__ float red[256];
        const float* src = (role == 0) ? n1a : (role == 1) ? n2a : (role == 2) ? g1 : g2;
        float* dst = (role == 0) ? g_v1a : (role == 1) ? g_v2a : (role == 2) ? g_g1 : g_g2;
        float m = 0.f;
        for (int i = tid; i < DIM; i += 256) m = fmaxf(m, fabsf(src[i]));
        red[tid] = m;
        __syncthreads();
        for (int s = 128; s > 0; s >>= 1) {
            if (tid < s) red[tid] = fmaxf(red[tid], red[tid + s]);
            __syncthreads();
        }
        float sc = __fadd_rn(__fdiv_rn(red[0], 127.f), 1e-8f);
        for (int i = tid; i < DIM; i += 256)
            dst[i] = __fmul_rn(sc, fqq(src[i], sc));
        return;
    }
    int seg = role - 4;
    const float* w; int n;
    if (seg == 0)      { w = w0; n = NTOK * NTOK; }
    else if (seg == 1) { w = w1; n = RNK * DIM; }
    else if (seg == 2) { w = w2; n = HID * RNK; }
    else if (seg == 3) { w = w3; n = RNK * HID; }
    else               { w = w4; n = DIM * RNK; }
    float m = 0.f;
    for (int i = blockIdx.x * blockDim.x + tid; i < n; i += gridDim.x * blockDim.x)
        m = fmaxf(m, fabsf(w[i]));
#pragma unroll
    for (int o = 16; o; o >>= 1) m = fmaxf(m, __shfl_xor_sync(0xffffffffu, m, o));
    if ((tid & 31) == 0)
        atomicMax((int*)&g_absmax[seg], __float_as_int(m));
}

__global__ void quantw_all_k(const float* __restrict__ w0, const float* __restrict__ w1,
                             const float* __restrict__ w2, const float* __restrict__ w3,
                             const float* __restrict__ w4) {
    int seg = blockIdx.y;
    float s = wscale(seg);
    if (seg == 0) {
        for (int i = blockIdx.x * blockDim.x + threadIdx.x; i < 256 * KPAD;
             i += gridDim.x * blockDim.x) {
            int m = i >> 8, k = i & (KPAD - 1);
            float v = 0.f;
            if (m < NTOK && k < NTOK) v = fqq(w0[m * NTOK + k], s);
            g_qWattn[i] = __float2bfloat16_rn(v);
        }
        return;
    }
    const float* w; bf16* dst; int n;
    if (seg == 1)      { w = w1; dst = g_qW1vt; n = RNK * DIM; }
    else if (seg == 2) { w = w2; dst = g_qW1u;  n = HID * RNK; }
    else if (seg == 3) { w = w3; dst = g_qW2vt; n = RNK * HID; }
    else               { w = w4; dst = g_qW2u;  n = DIM * RNK; }
    for (int i = blockIdx.x * blockDim.x + threadIdx.x; i < n;
         i += gridDim.x * blockDim.x)
        dst[i] = __float2bfloat16_rn(fqq(w[i], s));
}

// stage 0: qa1t[b][d][n] = fq(x[b,n,d]*fqw(norm1_a)[d]+norm1_b[d], s0)/s0
// tile: 64 tokens x 32 dims; paired bf162 stores along n.
__global__ void stage0_k(const float* __restrict__ x,
                         const float* __restrict__ nb1,
                         const float* __restrict__ sc) {
    __shared__ float tile[64][33];
    int d0 = blockIdx.x * 32, n0 = blockIdx.y * 64, b = blockIdx.z;
    float s0 = sc[0];
    int tx = threadIdx.x, ty = threadIdx.y;
#pragma unroll
    for (int r = 0; r < 8; ++r) {
        int nl = ty + r * 8;
        int n = n0 + nl, d = d0 + tx;
        float v = 0.f;
        if (n < NTOK) v = x[((long)b * NTOK + n) * DIM + d];
        tile[nl][tx] = v;
    }
    __syncthreads();
#pragma unroll
    for (int r = 0; r < 4; ++r) {
        int dl = ty + r * 8;
        int d = d0 + dl;
        float va = g_v1a[d], vb = nb1[d];
        int nl = tx * 2;
        float q0 = 0.f, q1 = 0.f;
        if (n0 + nl < NTOK)
            q0 = fqq(__fadd_rn(__fmul_rn(tile[nl][dl], va), vb), s0);
        if (n0 + nl + 1 < NTOK)
            q1 = fqq(__fadd_rn(__fmul_rn(tile[nl + 1][dl], va), vb), s0);
        *(bf162*)(g_qa1t + ((long)b * DIM + d) * KPAD + n0 + nl) =
            bf162(__float2bfloat16_rn(q0), __float2bfloat16_rn(q1));
    }
}

// ---------------------------------------------------------------------------
// bf16 HMMA GEMM core, parameterized: BM x BN tile, WRxWC warps, 2-stage smem
// ---------------------------------------------------------------------------

__device__ __forceinline__ unsigned s2u(const void* p) {
    return (unsigned)__cvta_generic_to_shared(p);
}
__device__ __forceinline__ void cp16(void* d, const void* s) {
    asm volatile("cp.async.cg.shared.global [%0], [%1], 16;\n"
                 :: "r"(s2u(d)), "l"(s) : "memory");
}
__device__ __forceinline__ void cpcommit() {
    asm volatile("cp.async.commit_group;\n" ::: "memory");
}
__device__ __forceinline__ void cpwait0() {
    asm volatile("cp.async.wait_group 0;\n" ::: "memory");
}
__device__ __forceinline__ void ldsm4(unsigned* r, const void* p) {
    asm volatile("ldmatrix.sync.aligned.m8n8.x4.shared.b16 {%0,%1,%2,%3}, [%4];\n"
                 : "=r"(r[0]), "=r"(r[1]), "=r"(r[2]), "=r"(r[3]) : "r"(s2u(p)));
}
__device__ __forceinline__ void mma_bf16(float* c, const unsigned* a,
                                         unsigned b0, unsigned b1) {
    asm volatile(
        "mma.sync.aligned.m16n8k16.row.col.f32.bf16.bf16.f32 "
        "{%0,%1,%2,%3},{%4,%5,%6,%7},{%8,%9},{%0,%1,%2,%3};\n"
        : "+f"(c[0]), "+f"(c[1]), "+f"(c[2]), "+f"(c[3])
        : "r"(a[0]), "r"(a[1]), "r"(a[2]), "r"(a[3]), "r"(b0), "r"(b1));
}

// XOR-swizzled smem address: 128B rows, chunk permuted by row
__device__ __forceinline__ int swz(int row, int chunk) {
    return row * 128 + (((chunk ^ row) & 7) << 4);
}

// STAGE: 0=attn(+res/norm2), 1=fc1_vt, 2=fc1_u(+GELU), 3=fc2_vt, 4=fc2_u(+out)
template <int STAGE, int BM, int BN, int WR, int WC, int OCC>
__global__ void __launch_bounds__(WR * WC * 32, OCC)
gemm_bf_k(int M, int N, int K,
          const float* __restrict__ sc,
          const float* __restrict__ bias,
          const float* __restrict__ xorg,
          const float* __restrict__ nb2,
          float* __restrict__ outf) {

    constexpr int THREADS = WR * WC * 32;
    constexpr int A_BYTES = BM * 128;
    constexpr int STAGE_BYTES = (BM + BN) * 128;
    constexpr int WM = BM / WR;               // warp tile rows
    constexpr int WN = BN / WC;               // warp tile cols
    constexpr int MI = WM / 16;
    constexpr int NJ = WN / 8;
    constexpr int NB = NJ / 2;
    constexpr int ACH = BM * 8 / THREADS;     // A chunks per thread
    constexpr int BCH = BN * 8 / THREADS;     // B chunks per thread

    extern __shared__ __align__(256) int8_t dsm[];

    const int tid  = threadIdx.x;
    const int warp = tid >> 5, lane = tid & 31;
    const int wm = warp / WC, wn = warp % WC;
    const int m0 = blockIdx.y * BM;
    const int n0 = blockIdx.x * BN;
    const int bz = blockIdx.z;

    const bf16* Ab;
    const bf16* Bb;
    if (STAGE == 0)      { Ab = g_qWattn; Bb = g_qa1t + (long)bz * DIM * KPAD; }
    else if (STAGE == 1) { Ab = g_qa2;    Bb = g_qW1vt; }
    else if (STAGE == 2) { Ab = g_qa3;    Bb = g_qW1u; }
    else if (STAGE == 3) { Ab = g_qa4;    Bb = g_qW2vt; }
    else                 { Ab = g_qa5;    Bb = g_qW2u; }

    const long rowBytes = (long)K * 2;

    // loader: thread t handles chunks [t*ACH, t*ACH+ACH) of A (8 chunks/row)
    const int aRowL = (tid * ACH) >> 3, aCbL = (tid * ACH) & 7;
    const int bRowL = (tid * BCH) >> 3, bCbL = (tid * BCH) & 7;

    const int8_t* agp = (const int8_t*)Ab + (long)(m0 + aRowL) * rowBytes + aCbL * 16;
    const int8_t* bgp = (const int8_t*)Bb + (long)(n0 + bRowL) * rowBytes + bCbL * 16;

    int sA[ACH], sB[BCH];
#pragma unroll
    for (int c = 0; c < ACH; ++c) sA[c] = swz(aRowL, aCbL + c);
#pragma unroll
    for (int c = 0; c < BCH; ++c) sB[c] = swz(bRowL, bCbL + c) + A_BYTES;

    auto loadTile = [&](int buf) {
        int8_t* base = dsm + buf * STAGE_BYTES;
#pragma unroll
        for (int c = 0; c < ACH; ++c) cp16(base + sA[c], agp + c * 16);
#pragma unroll
        for (int c = 0; c < BCH; ++c) cp16(base + sB[c], bgp + c * 16);
        cpcommit();
        agp += 128;
        bgp += 128;
    };

    float acc[MI][NJ][4];
#pragma unroll
    for (int i = 0; i < MI; ++i)
#pragma unroll
        for (int j = 0; j < NJ; ++j)
#pragma unroll
            for (int t = 0; t < 4; ++t) acc[i][j][t] = 0.f;

    const int ktiles = K >> 6;      // 64 elements (128B) per k-tile
    loadTile(0);

    const int aRow = lane & 15;
    const int bRow = (lane & 7) + ((lane >> 3) & 1) * 8;
    const int cLane = lane >> 4;

    for (int kt = 0; kt < ktiles; ++kt) {
        cpwait0();
        __syncthreads();               // also orders buffer reuse
        if (kt + 1 < ktiles) loadTile((kt + 1) & 1);

        int8_t* as = dsm + (kt & 1) * STAGE_BYTES;
        int8_t* bs = as + A_BYTES;

#pragma unroll
        for (int ks = 0; ks < 4; ++ks) {       // 4 x k16 per tile
            unsigned a[MI][4], b[NB][4];
#pragma unroll
            for (int i = 0; i < MI; ++i)
                ldsm4(a[i], as + swz(wm * WM + i * 16 + aRow, ks * 2 + cLane));
#pragma unroll
            for (int jp = 0; jp < NB; ++jp)
                ldsm4(b[jp], bs + swz(wn * WN + jp * 16 + bRow, ks * 2 + cLane));
#pragma unroll
            for (int jp = 0; jp < NB; ++jp)
#pragma unroll
                for (int i = 0; i < MI; ++i) {
                    mma_bf16(acc[i][jp * 2 + 0], a[i], b[jp][0], b[jp][2]);
                    mma_bf16(acc[i][jp * 2 + 1], a[i], b[jp][1], b[jp][3]);
                }
        }
    }

    // ---- epilogue ----
    const float sc1 = sc[1], sc2 = sc[2], sc3 = sc[3], sc4 = sc[4];
    const float sc5 = sc[5], sc6 = sc[6], sc7 = sc[7], sc8 = sc[8], sc9 = sc[9];
    float swp;
    if (STAGE == 0)      swp = sc[0] * wscale(0);
    else if (STAGE == 1) swp = sc2 * wscale(1);
    else if (STAGE == 2) swp = sc4 * wscale(2);
    else if (STAGE == 3) swp = sc6 * wscale(3);
    else                 swp = sc7 * wscale(4);

#pragma unroll
    for (int i = 0; i < MI; ++i) {
        int mrow = m0 + wm * WM + i * 16 + (lane >> 2);
#pragma unroll
        for (int j = 0; j < NJ; ++j) {
            int nn = n0 + wn * WN + j * 8 + ((lane & 3) << 1);
#pragma unroll
            for (int h = 0; h < 2; ++h) {
                int mm = mrow + h * 8;
                if (mm >= M) continue;
                float a0 = acc[i][j][h * 2 + 0];
                float a1 = acc[i][j][h * 2 + 1];

                if (STAGE == 0) {
                    float bm = bias[mm];
                    float v0 = __fadd_rn(__fmul_rn(a0, swp), bm);
                    float v1 = __fadd_rn(__fmul_rn(a1, swp), bm);
                    float t0 = __fmul_rn(__fmul_rn(sc1, fqq(v0, sc1)), g_g1[nn]);
                    float t1 = __fmul_rn(__fmul_rn(sc1, fqq(v1, sc1)), g_g1[nn + 1]);
                    long idx = ((long)bz * NTOK + mm) * DIM + nn;
                    float2 xo = *(const float2*)(xorg + idx);
                    float q80 = fqq(__fadd_rn(t0, xo.x), sc8);
                    float q81 = fqq(__fadd_rn(t1, xo.y), sc8);
                    *(bf162*)(g_qx1 + idx) =
                        bf162(__float2bfloat16_rn(q80), __float2bfloat16_rn(q81));
                    float x10 = __fmul_rn(sc8, q80), x11 = __fmul_rn(sc8, q81);
                    float h0 = __fadd_rn(__fmul_rn(x10, g_v2a[nn]),     nb2[nn]);
                    float h1 = __fadd_rn(__fmul_rn(x11, g_v2a[nn + 1]), nb2[nn + 1]);
                    *(bf162*)(g_qa2 + idx) =
                        bf162(__float2bfloat16_rn(fqq(h0, sc2)),
                              __float2bfloat16_rn(fqq(h1, sc2)));
                } else if (STAGE == 1 || STAGE == 3) {
                    bf16* dst = (STAGE == 1) ? g_qa3 : g_qa5;
                    float scq = (STAGE == 1) ? sc4 : sc7;
                    float v0 = __fadd_rn(__fmul_rn(a0, swp), bias[nn]);
                    float v1 = __fadd_rn(__fmul_rn(a1, swp), bias[nn + 1]);
                    *(bf162*)(dst + (long)mm * RNK + nn) =
                        bf162(__float2bfloat16_rn(fqq(v0, scq)),
                              __float2bfloat16_rn(fqq(v1, scq)));
                } else if (STAGE == 2) {
                    float v0 = __fadd_rn(__fmul_rn(a0, swp), bias[nn]);
                    float v1 = __fadd_rn(__fmul_rn(a1, swp), bias[nn + 1]);
                    float t0 = __fmul_rn(sc5, fqq(v0, sc5));
                    float t1 = __fmul_rn(sc5, fqq(v1, sc5));
                    float g0 = __fmul_rn(__fmul_rn(0.5f, t0),
                               __fadd_rn(1.f, erff(__fmul_rn(t0, 0.70710678118654752f))));
                    float g1v = __fmul_rn(__fmul_rn(0.5f, t1),
                               __fadd_rn(1.f, erff(__fmul_rn(t1, 0.70710678118654752f))));
                    *(bf162*)(g_qa4 + (long)mm * HID + nn) =
                        bf162(__float2bfloat16_rn(fqq(g0, sc6)),
                              __float2bfloat16_rn(fqq(g1v, sc6)));
                } else {
                    float v0 = __fadd_rn(__fmul_rn(a0, swp), bias[nn]);
                    float v1 = __fadd_rn(__fmul_rn(a1, swp), bias[nn + 1]);
                    float t0 = __fmul_rn(__fmul_rn(sc3, fqq(v0, sc3)), g_g2[nn]);
                    float t1 = __fmul_rn(__fmul_rn(sc3, fqq(v1, sc3)), g_g2[nn + 1]);
                    long idx = (long)mm * DIM + nn;
                    bf162 qx = *(const bf162*)(g_qx1 + idx);
                    float r0 = __fadd_rn(t0, __fmul_rn(sc8, __bfloat162float(qx.x)));
                    float r1 = __fadd_rn(t1, __fmul_rn(sc8, __bfloat162float(qx.y)));
                    float2 o;
                    o.x = __fmul_rn(sc9, fqq(r0, sc9));
                    o.y = __fmul_rn(sc9, fqq(r1, sc9));
                    *(float2*)(outf + idx) = o;
                }
            }
        }
    }
}

constexpr int SMEM_ATTN = 2 * (64 + 64) * 128;     // 32768
constexpr int SMEM_FC   = 2 * (128 + 128) * 128;   // 65536

} // anonymous namespace

// ---------------------------------------------------------------------------
extern "C" void kernel_launch(void* const* d_in, const int* in_sizes, int n_in,
                              void* d_out, int out_size) {
    const float* x    = (const float*)d_in[0];
    const float* n1a  = (const float*)d_in[1];
    const float* n1b  = (const float*)d_in[2];
    const float* attw = (const float*)d_in[3];
    const float* attb = (const float*)d_in[4];
    const float* g1   = (const float*)d_in[5];
    const float* n2a  = (const float*)d_in[6];
    const float* n2b  = (const float*)d_in[7];
    const float* w1vt = (const float*)d_in[8];
    const float* b1vt = (const float*)d_in[9];
    const float* w1u  = (const float*)d_in[10];
    const float* b1u  = (const float*)d_in[11];
    const float* w2vt = (const float*)d_in[12];
    const float* b2vt = (const float*)d_in[13];
    const float* w2u  = (const float*)d_in[14];
    const float* b2u  = (const float*)d_in[15];
    const float* g2   = (const float*)d_in[16];
    const float* sc   = (const float*)d_in[17];
    float* out = (float*)d_out;

    cudaFuncSetAttribute((const void*)gemm_bf_k<0, 64, 64, 2, 4, 6>,
                         cudaFuncAttributeMaxDynamicSharedMemorySize, SMEM_ATTN);
    cudaFuncSetAttribute((const void*)gemm_bf_k<1, 128, 128, 4, 4, 2>,
                         cudaFuncAttributeMaxDynamicSharedMemorySize, SMEM_FC);
    cudaFuncSetAttribute((const void*)gemm_bf_k<2, 128, 128, 4, 4, 2>,
                         cudaFuncAttributeMaxDynamicSharedMemorySize, SMEM_FC);
    cudaFuncSetAttribute((const void*)gemm_bf_k<3, 128, 128, 4, 4, 2>,
                         cudaFuncAttributeMaxDynamicSharedMemorySize, SMEM_FC);
    cudaFuncSetAttribute((const void*)gemm_bf_k<4, 128, 128, 4, 4, 2>,
                         cudaFuncAttributeMaxDynamicSharedMemorySize, SMEM_FC);

    prep1_k<<<dim3(96, 9), 256>>>(n1a, n2a, g1, g2, attw, w1vt, w1u, w2vt, w2u);
    quantw_all_k<<<dim3(128, 5), 256>>>(attw, w1vt, w1u, w2vt, w2u);

    {   // stage 0: norm1 + fq(s0), transposed/padded to [b][d][256]
        dim3 grid(DIM / 32, KPAD / 64, BATCH);
        dim3 blk(32, 8);
        stage0_k<<<grid, blk>>>(x, n1b, sc);
    }
    {   // attn: per-batch C[196,768], K=256 — 64x64 @6 CTAs/SM
        dim3 grid(DIM / 64, 4, BATCH);
        gemm_bf_k<0, 64, 64, 2, 4, 6><<<grid, 256, SMEM_ATTN>>>(
            NTOK, DIM, KPAD, sc, attb, x, n2b, nullptr);
    }
    {   // fc1_vt — 128x128 @2 CTAs/SM, 512 threads
        dim3 grid(RNK / 128, (int)(TROWS / 128), 1);
        gemm_bf_k<1, 128, 128, 4, 4, 2><<<grid, 512, SMEM_FC>>>(
            (int)TROWS, RNK, DIM, sc, b1vt, x, n2b, nullptr);
    }
    {   // fc1_u (+GELU)
        dim3 grid(HID / 128, (int)(TROWS / 128), 1);
        gemm_bf_k<2, 128, 128, 4, 4, 2><<<grid, 512, SMEM_FC>>>(
            (int)TROWS, HID, RNK, sc, b1u, x, n2b, nullptr);
    }
    {   // fc2_vt
        dim3 grid(RNK / 128, (int)(TROWS / 128), 1);
        gemm_bf_k<3, 128, 128, 4, 4, 2><<<grid, 512, SMEM_FC>>>(
            (int)TROWS, RNK, HID, sc, b2vt, x, n2b, nullptr);
    }
    {   // fc2_u + gamma2 + residual -> out
        dim3 grid(DIM / 128, (int)(TROWS / 128), 1);
        gemm_bf_k<4, 128, 128, 4, 4, 2><<<grid, 512, SMEM_FC>>>(
            (int)TROWS, DIM, RNK, sc, b2u, x, n2b, out);
    }
}